// round 6
// baseline (speedup 1.0000x reference)
#include <cuda_runtime.h>

#define NN 50000
#define NE 800000
#define NF 256
#define NCLS 47

typedef unsigned long long u64;

// ---------------- scratch (device globals; no allocation allowed) ----------
__device__ __align__(16) float g_h1[NN * NF];   // layer outputs / logits reuse
__device__ __align__(16) float g_h2[NN * NF];
__device__ __align__(16) float g_hm[NN * NF];   // hmean buffer
__device__ float g_rdeg[NN];
__device__ int   g_rowstart[NN + 1];
__device__ int   g_cursor[NN];
__device__ int   g_adj[NE];
__device__ int   g_cnt[NN];

__device__ __forceinline__ const float* sel_src(int sel, const float* x) {
    if (sel == 0) return x;
    if (sel == 1) return g_h1;
    return g_h2;
}
__device__ __forceinline__ float* sel_dst(int sel) {
    return (sel == 1) ? g_h1 : g_h2;
}

// packed f32x2 helpers (Blackwell FFMA2 — only reachable via PTX)
__device__ __forceinline__ void fma_f32x2(u64& d, u64 a, u64 b) {
    asm("fma.rn.f32x2 %0, %1, %2, %0;" : "+l"(d) : "l"(a), "l"(b));
}
__device__ __forceinline__ u64 pack_f32x2(float lo, float hi) {
    u64 r;
    asm("mov.b64 %0, {%1, %2};" : "=l"(r) : "f"(lo), "f"(hi));
    return r;
}
__device__ __forceinline__ void unpack_f32x2(u64 v, float& lo, float& hi) {
    asm("mov.b64 {%0, %1}, %2;" : "=f"(lo), "=f"(hi) : "l"(v));
}

// ---------------- CSR build ----------------
__global__ void k_zero_cnt() {
    int i = blockIdx.x * blockDim.x + threadIdx.x;
    if (i < NN) g_cnt[i] = 0;
}

__global__ void k_count(const int* __restrict__ dst) {
    int e = blockIdx.x * blockDim.x + threadIdx.x;
    if (e < NE) {
        int d = dst[e];
        if (d >= 0 && d < NN) atomicAdd(&g_cnt[d], 1);
    }
}

__global__ void k_scan() {
    __shared__ int sbuf[1024];
    __shared__ int s_total;
    int tid = threadIdx.x;
    if (tid == 0) s_total = 0;
    __syncthreads();
    for (int base = 0; base < NN; base += 1024) {
        int i = base + tid;
        int v = (i < NN) ? g_cnt[i] : 0;
        sbuf[tid] = v;
        __syncthreads();
        for (int off = 1; off < 1024; off <<= 1) {
            int tval = (tid >= off) ? sbuf[tid - off] : 0;
            __syncthreads();
            sbuf[tid] += tval;
            __syncthreads();
        }
        int incl = sbuf[tid];
        int excl = incl - v;
        if (i < NN) {
            int rs = s_total + excl;
            g_rowstart[i] = rs;
            g_cursor[i]   = rs;
            g_rdeg[i]     = 1.0f / fmaxf((float)v, 1.0f);
        }
        __syncthreads();
        if (tid == 1023) s_total += incl;
        __syncthreads();
    }
    if (tid == 0) g_rowstart[NN] = s_total;
}

__global__ void k_fill(const int* __restrict__ src,
                       const int* __restrict__ dst) {
    int e = blockIdx.x * blockDim.x + threadIdx.x;
    if (e < NE) {
        int d = dst[e];
        int s = src[e];
        if (d >= 0 && d < NN && s >= 0 && s < NN) {
            int pos = atomicAdd(&g_cursor[d], 1);
            if (pos >= 0 && pos < NE) g_adj[pos] = s;
        }
    }
}

// ---------------- mean aggregation: one warp per node --------------------
__global__ void k_aggregate(int src_sel, const float* __restrict__ x) {
    const float* h = sel_src(src_sel, x);
    int w = (blockIdx.x * blockDim.x + threadIdx.x) >> 5;
    int lane = threadIdx.x & 31;
    if (w >= NN) return;
    int s0 = g_rowstart[w];
    int s1 = g_rowstart[w + 1];
    float4 a0 = make_float4(0.f, 0.f, 0.f, 0.f);
    float4 a1 = make_float4(0.f, 0.f, 0.f, 0.f);
    for (int j = s0; j < s1; j++) {
        int s = g_adj[j];
        const float4* row = (const float4*)(h + (size_t)s * NF);
        float4 v0 = row[lane];
        float4 v1 = row[lane + 32];
        a0.x += v0.x; a0.y += v0.y; a0.z += v0.z; a0.w += v0.w;
        a1.x += v1.x; a1.y += v1.y; a1.z += v1.z; a1.w += v1.w;
    }
    float r = g_rdeg[w];
    a0.x *= r; a0.y *= r; a0.z *= r; a0.w *= r;
    a1.x *= r; a1.y *= r; a1.z *= r; a1.w *= r;
    float4* o = (float4*)(g_hm + (size_t)w * NF);
    o[lane] = a0;
    o[lane + 32] = a1;
}

// ---------------- fused GEMM (FFMA2): C = [A|hmean] @ [Bw;Bn] + b (+SELU) --
// BM=128, BN=64, BK=16, 256 threads, 8x4 micro-tile as 4x(2)x4 f32x2.
// As: [k][m] so adjacent m-rows pack into u64 for free.
// Bs2: duplicated {b,b} u64 per column so the broadcast multiplier is one LDS.64.
__global__ void __launch_bounds__(256)
k_gemm(int a_sel, const float* __restrict__ x,
       const float* __restrict__ Bw, const float* __restrict__ Bn,
       const float* __restrict__ bias, int c_sel,
       int M, int Nc, int act) {
    const float* A  = sel_src(a_sel, x);
    const float* Am = g_hm;
    float* Cout = sel_dst(c_sel);

    __shared__ float As[16][128];
    __shared__ u64   Bs2[16][64];

    int t  = threadIdx.x;
    int tm = t >> 4;        // 0..15
    int tn = t & 15;        // 0..15
    int bm = blockIdx.x * 128;
    int bn = blockIdx.y * 64;

    u64 acc2[4][4];         // [row-pair][col], each holds {row 2i, row 2i+1}
#pragma unroll
    for (int i = 0; i < 4; i++)
#pragma unroll
        for (int j = 0; j < 4; j++) acc2[i][j] = 0ull;

    int arow = t >> 1;            // 0..127
    int kofs = (t & 1) * 8;       // 0 or 8
    int bk   = t >> 4;            // 0..15
    int bnl  = (t & 15) * 4;      // 0..60

    for (int kt = 0; kt < 32; kt++) {
        const float* Ap = (kt < 16) ? A : Am;
        const float* Bp = (kt < 16) ? Bw : Bn;
        int kb = (kt & 15) * 16;

        float4 va0 = make_float4(0.f, 0.f, 0.f, 0.f);
        float4 va1 = make_float4(0.f, 0.f, 0.f, 0.f);
        int m = bm + arow;
        if (m < M) {
            const float* p = Ap + (size_t)m * NF + kb + kofs;
            va0 = *(const float4*)p;
            va1 = *(const float4*)(p + 4);
        }
        float vb[4];
        {
            int krow = kb + bk;
            const float* p = Bp + (size_t)krow * Nc;
#pragma unroll
            for (int j = 0; j < 4; j++) {
                int c = bn + bnl + j;
                vb[j] = (c < Nc) ? p[c] : 0.f;
            }
        }

        __syncthreads();
        As[kofs + 0][arow] = va0.x;
        As[kofs + 1][arow] = va0.y;
        As[kofs + 2][arow] = va0.z;
        As[kofs + 3][arow] = va0.w;
        As[kofs + 4][arow] = va1.x;
        As[kofs + 5][arow] = va1.y;
        As[kofs + 6][arow] = va1.z;
        As[kofs + 7][arow] = va1.w;
#pragma unroll
        for (int j = 0; j < 4; j++) Bs2[bk][bnl + j] = pack_f32x2(vb[j], vb[j]);
        __syncthreads();

#pragma unroll
        for (int kk = 0; kk < 16; kk++) {
            const u64* pa = (const u64*)&As[kk][tm * 8];
            u64 a0 = pa[0], a1 = pa[1], a2 = pa[2], a3 = pa[3];
            const u64* pb = &Bs2[kk][tn * 4];
            u64 b0 = pb[0], b1 = pb[1], b2 = pb[2], b3 = pb[3];
            fma_f32x2(acc2[0][0], a0, b0); fma_f32x2(acc2[0][1], a0, b1);
            fma_f32x2(acc2[0][2], a0, b2); fma_f32x2(acc2[0][3], a0, b3);
            fma_f32x2(acc2[1][0], a1, b0); fma_f32x2(acc2[1][1], a1, b1);
            fma_f32x2(acc2[1][2], a1, b2); fma_f32x2(acc2[1][3], a1, b3);
            fma_f32x2(acc2[2][0], a2, b0); fma_f32x2(acc2[2][1], a2, b1);
            fma_f32x2(acc2[2][2], a2, b2); fma_f32x2(acc2[2][3], a2, b3);
            fma_f32x2(acc2[3][0], a3, b0); fma_f32x2(acc2[3][1], a3, b1);
            fma_f32x2(acc2[3][2], a3, b2); fma_f32x2(acc2[3][3], a3, b3);
        }
    }

    const float kAlpha  = 1.6732632423543772f;
    const float kLambda = 1.0507009873554805f;
#pragma unroll
    for (int i2 = 0; i2 < 4; i2++) {
#pragma unroll
        for (int j = 0; j < 4; j++) {
            int c = bn + tn * 4 + j;
            if (c >= Nc) continue;
            float lo, hi;
            unpack_f32x2(acc2[i2][j], lo, hi);
            float bsv = bias[c];
            int m0 = bm + tm * 8 + 2 * i2;
            int m1 = m0 + 1;
            float v0 = lo + bsv;
            float v1 = hi + bsv;
            if (act == 1) {
                v0 = (v0 > 0.f) ? kLambda * v0 : kLambda * kAlpha * (expf(v0) - 1.f);
                v1 = (v1 > 0.f) ? kLambda * v1 : kLambda * kAlpha * (expf(v1) - 1.f);
            }
            if (m0 < M) Cout[(size_t)m0 * Nc + c] = v0;
            if (m1 < M) Cout[(size_t)m1 * Nc + c] = v1;
        }
    }
}

// ---------------- softmax over 47 classes (logits in g_h1) -----------------
__global__ void k_softmax(float* __restrict__ out) {
    int w = (blockIdx.x * blockDim.x + threadIdx.x) >> 5;
    int lane = threadIdx.x & 31;
    if (w >= NN) return;
    const float* z = g_h1 + (size_t)w * NCLS;
    float v0 = (lane < NCLS) ? z[lane] : -1e30f;
    float v1 = (lane + 32 < NCLS) ? z[lane + 32] : -1e30f;
    float m = fmaxf(v0, v1);
#pragma unroll
    for (int o = 16; o; o >>= 1) m = fmaxf(m, __shfl_xor_sync(0xffffffffu, m, o));
    float e0 = (lane < NCLS) ? expf(v0 - m) : 0.f;
    float e1 = (lane + 32 < NCLS) ? expf(v1 - m) : 0.f;
    float s = e0 + e1;
#pragma unroll
    for (int o = 16; o; o >>= 1) s += __shfl_xor_sync(0xffffffffu, s, o);
    float inv = 1.f / s;
    if (lane < NCLS)       out[(size_t)w * NCLS + lane]      = e0 * inv;
    if (lane + 32 < NCLS)  out[(size_t)w * NCLS + lane + 32] = e1 * inv;
}

// ---------------- launch ---------------------------------------------------
extern "C" void kernel_launch(void* const* d_in, const int* in_sizes, int n_in,
                              void* d_out, int out_size) {
    const float* x   = (const float*)d_in[0];
    const int*   src = (const int*)d_in[1];    // int32 edge indices
    const int*   dst = (const int*)d_in[2];
    const float* Ws0 = (const float*)d_in[3];
    const float* Wn0 = (const float*)d_in[4];
    const float* b0  = (const float*)d_in[5];
    const float* Ws1 = (const float*)d_in[6];
    const float* Wn1 = (const float*)d_in[7];
    const float* b1  = (const float*)d_in[8];
    const float* Ws2 = (const float*)d_in[9];
    const float* Wn2 = (const float*)d_in[10];
    const float* b2  = (const float*)d_in[11];
    float* out = (float*)d_out;

    // CSR build (per call)
    k_zero_cnt<<<(NN + 255) / 256, 256>>>();
    k_count<<<(NE + 255) / 256, 256>>>(dst);
    k_scan<<<1, 1024>>>();
    k_fill<<<(NE + 255) / 256, 256>>>(src, dst);

    dim3 gemm_grid_full((NN + 127) / 128, NF / 64);
    dim3 gemm_grid_last((NN + 127) / 128, 1);
    int agg_blocks = (NN + 7) / 8;

    // layer 0: x -> g_h1
    k_aggregate<<<agg_blocks, 256>>>(0, x);
    k_gemm<<<gemm_grid_full, 256>>>(0, x, Ws0, Wn0, b0, 1, NN, NF, 1);

    // layer 1: g_h1 -> g_h2
    k_aggregate<<<agg_blocks, 256>>>(1, x);
    k_gemm<<<gemm_grid_full, 256>>>(1, x, Ws1, Wn1, b1, 2, NN, NF, 1);

    // layer 2: g_h2 -> logits in g_h1
    k_aggregate<<<agg_blocks, 256>>>(2, x);
    k_gemm<<<gemm_grid_last, 256>>>(2, x, Ws2, Wn2, b2, 1, NN, NCLS, 0);

    // softmax -> d_out
    k_softmax<<<agg_blocks, 256>>>(out);
}